// round 1
// baseline (speedup 1.0000x reference)
#include <cuda_runtime.h>
#include <cstdint>
#include <cstddef>

// ---------------------------------------------------------------------------
// MultiHeadAttention: x[4,2048,1024] -> out[4,2048,1024]
//   qkv = x @ W_qkv + b_qkv          (8192 x 3072, K=1024)
//   flash attention per (b,h)        (T=2048, d=64, 16 heads)
//   out = ctx @ W_out + b_out        (8192 x 1024, K=1024)
// All matmuls: tf32 mma.sync.m16n8k8 with fp32 accumulate.
// ---------------------------------------------------------------------------

#define B_   4
#define T_   2048
#define E_   1024
#define H_   16
#define D_   64
#define M_ROWS (B_ * T_)          // 8192
#define QKV_N  (3 * E_)           // 3072

// Scratch (no allocations allowed -> __device__ globals)
static __device__ float g_qkv[(size_t)M_ROWS * QKV_N];   // ~100.7 MB
static __device__ float g_ctx[(size_t)M_ROWS * E_];      // ~33.6 MB

// ---------------------------------------------------------------------------
// helpers
// ---------------------------------------------------------------------------
__device__ __forceinline__ uint32_t f2tf(float f) {
    uint32_t u;
    asm("cvt.rna.tf32.f32 %0, %1;" : "=r"(u) : "f"(f));
    return u;
}

__device__ __forceinline__ void mma_tf32(float c[4],
                                         uint32_t a0, uint32_t a1, uint32_t a2, uint32_t a3,
                                         uint32_t b0, uint32_t b1) {
    asm volatile(
        "mma.sync.aligned.m16n8k8.row.col.f32.tf32.tf32.f32 "
        "{%0,%1,%2,%3}, {%4,%5,%6,%7}, {%8,%9}, {%0,%1,%2,%3};"
        : "+f"(c[0]), "+f"(c[1]), "+f"(c[2]), "+f"(c[3])
        : "r"(a0), "r"(a1), "r"(a2), "r"(a3), "r"(b0), "r"(b1));
}

// FMA-only exp (avoids MUFU bottleneck: 268M exps in softmax).
// |rel err| ~ 2e-6 on [-87, 0].
__device__ __forceinline__ float fast_exp(float x) {
    x = fmaxf(x, -87.0f);
    const float L2E = 1.4426950408889634f;
    float z  = fmaf(x, L2E, 12582912.0f);          // round(x*log2e) via magic
    int   ni = __float_as_int(z) - 0x4B400000;     // integer part n
    float n  = z - 12582912.0f;
    float f  = fmaf(x, L2E, -n);                   // f in [-0.5, 0.5]
    float p  = fmaf(f, 0.0013333558f, 0.0096181291f);
    p = fmaf(f, p, 0.0555041087f);
    p = fmaf(f, p, 0.2402265070f);
    p = fmaf(f, p, 0.6931471806f);
    p = fmaf(f, p, 1.0f);                          // exp2(f)
    return p * __int_as_float((ni + 127) << 23);   // * 2^n
}

// ---------------------------------------------------------------------------
// GEMM: C[M,N] = A[M,K] @ W[K,N] + bias[N]   (tf32 mma, 128x128x32 tiles)
// 256 threads = 8 warps (2 x 4), warp tile 64x32.
// ---------------------------------------------------------------------------
#define GA_STRIDE 40   // As pitch: bank = (8r + c) % 32 -> conflict-free frag reads
#define GB_STRIDE 136  // Bs pitch: bank = (8k + n) % 32 -> conflict-free frag reads

__global__ __launch_bounds__(256)
void gemm_bias_kernel(const float* __restrict__ A, const float* __restrict__ W,
                      const float* __restrict__ bias, float* __restrict__ C,
                      int M, int N, int K) {
    __shared__ __align__(16) float As[128 * GA_STRIDE];
    __shared__ __align__(16) float Bs[32 * GB_STRIDE];

    const int tid   = threadIdx.x;
    const int lane  = tid & 31;
    const int w     = tid >> 5;
    const int g     = lane >> 2;     // 0..7
    const int t4    = lane & 3;      // 0..3
    const int warpM = w >> 2;        // 0..1
    const int warpN = w & 3;         // 0..3
    const int bm    = blockIdx.y * 128;
    const int bn    = blockIdx.x * 128;

    float c[4][4][4];
#pragma unroll
    for (int mt = 0; mt < 4; mt++)
#pragma unroll
        for (int nt = 0; nt < 4; nt++)
#pragma unroll
            for (int r = 0; r < 4; r++) c[mt][nt][r] = 0.0f;

    const int am  = tid >> 3;        // 0..31 (row within pass)
    const int ak  = (tid & 7) * 4;   // 0..28 step 4
    const int bn4 = tid & 31;        // float4 column
    const int bk  = tid >> 5;        // 0..7

    for (int k0 = 0; k0 < K; k0 += 32) {
        // stage A (rows bm..bm+127, cols k0..k0+31), convert to tf32
#pragma unroll
        for (int p = 0; p < 4; p++) {
            const int m = am + p * 32;
            float4 v = *reinterpret_cast<const float4*>(&A[(size_t)(bm + m) * K + k0 + ak]);
            As[m * GA_STRIDE + ak + 0] = __uint_as_float(f2tf(v.x));
            As[m * GA_STRIDE + ak + 1] = __uint_as_float(f2tf(v.y));
            As[m * GA_STRIDE + ak + 2] = __uint_as_float(f2tf(v.z));
            As[m * GA_STRIDE + ak + 3] = __uint_as_float(f2tf(v.w));
        }
        // stage B (rows k0..k0+31, cols bn..bn+127)
#pragma unroll
        for (int p = 0; p < 4; p++) {
            const int kk = bk + p * 8;
            float4 v = *reinterpret_cast<const float4*>(&W[(size_t)(k0 + kk) * N + bn + bn4 * 4]);
            float4 o;
            o.x = __uint_as_float(f2tf(v.x));
            o.y = __uint_as_float(f2tf(v.y));
            o.z = __uint_as_float(f2tf(v.z));
            o.w = __uint_as_float(f2tf(v.w));
            *reinterpret_cast<float4*>(&Bs[kk * GB_STRIDE + bn4 * 4]) = o;
        }
        __syncthreads();

#pragma unroll
        for (int ks = 0; ks < 4; ks++) {
            uint32_t a[4][4];
#pragma unroll
            for (int mt = 0; mt < 4; mt++) {
                const int r = warpM * 64 + mt * 16 + g;
                a[mt][0] = __float_as_uint(As[r * GA_STRIDE + ks * 8 + t4]);
                a[mt][1] = __float_as_uint(As[(r + 8) * GA_STRIDE + ks * 8 + t4]);
                a[mt][2] = __float_as_uint(As[r * GA_STRIDE + ks * 8 + t4 + 4]);
                a[mt][3] = __float_as_uint(As[(r + 8) * GA_STRIDE + ks * 8 + t4 + 4]);
            }
            uint32_t bf[4][2];
#pragma unroll
            for (int nt = 0; nt < 4; nt++) {
                const int cn = warpN * 32 + nt * 8 + g;
                bf[nt][0] = __float_as_uint(Bs[(ks * 8 + t4) * GB_STRIDE + cn]);
                bf[nt][1] = __float_as_uint(Bs[(ks * 8 + t4 + 4) * GB_STRIDE + cn]);
            }
#pragma unroll
            for (int mt = 0; mt < 4; mt++)
#pragma unroll
                for (int nt = 0; nt < 4; nt++)
                    mma_tf32(c[mt][nt], a[mt][0], a[mt][1], a[mt][2], a[mt][3],
                             bf[nt][0], bf[nt][1]);
        }
        __syncthreads();
    }

    // epilogue: bias + store
#pragma unroll
    for (int mt = 0; mt < 4; mt++) {
        const int r0 = bm + warpM * 64 + mt * 16 + g;
#pragma unroll
        for (int nt = 0; nt < 4; nt++) {
            const int cn = bn + warpN * 32 + nt * 8 + 2 * t4;
            const float bv0 = bias[cn], bv1 = bias[cn + 1];
            C[(size_t)r0 * N + cn]           = c[mt][nt][0] + bv0;
            C[(size_t)r0 * N + cn + 1]       = c[mt][nt][1] + bv1;
            C[(size_t)(r0 + 8) * N + cn]     = c[mt][nt][2] + bv0;
            C[(size_t)(r0 + 8) * N + cn + 1] = c[mt][nt][3] + bv1;
        }
    }
}

// ---------------------------------------------------------------------------
// Flash attention. Block = (b, h, 64 q-rows). 128 threads (4 warps, 16 q each).
// kv tiled 64-wide; S and P@V both via tf32 mma; online softmax, FMA-exp.
// smem pitch 72: bank = (8r + c) % 32 for all fragment patterns -> conflict-free.
// ---------------------------------------------------------------------------
#define AT_STRIDE 72
#define ATTN_SMEM ((4 * 64 * AT_STRIDE + 64) * 4)

__global__ __launch_bounds__(128)
void attn_kernel(const float* __restrict__ qkv, const int* __restrict__ mask,
                 float* __restrict__ ctx) {
    extern __shared__ float sm[];
    float* Qs = sm;
    float* Ks = sm + 64 * AT_STRIDE;
    float* Vs = sm + 2 * 64 * AT_STRIDE;
    float* Ps = sm + 3 * 64 * AT_STRIDE;           // per-warp 16-row regions
    int*   mk = (int*)(sm + 4 * 64 * AT_STRIDE);   // 64 mask ints

    const int b  = blockIdx.z;
    const int h  = blockIdx.y;
    const int q0 = blockIdx.x * 64;
    const int tid = threadIdx.x, lane = tid & 31, w = tid >> 5;
    const int g = lane >> 2, t4 = lane & 3;

    const float* base = qkv + (size_t)b * T_ * QKV_N + h * D_;

    // load Q tile (scaled by 1/sqrt(d) = 0.125, folded into Q)
    {
        const int r  = tid >> 1;
        const int c0 = (tid & 1) * 32;
        const float* src = base + (size_t)(q0 + r) * QKV_N + c0;
#pragma unroll
        for (int j = 0; j < 8; j++) {
            float4 v = *reinterpret_cast<const float4*>(src + j * 4);
            Qs[r * AT_STRIDE + c0 + j * 4 + 0] = __uint_as_float(f2tf(v.x * 0.125f));
            Qs[r * AT_STRIDE + c0 + j * 4 + 1] = __uint_as_float(f2tf(v.y * 0.125f));
            Qs[r * AT_STRIDE + c0 + j * 4 + 2] = __uint_as_float(f2tf(v.z * 0.125f));
            Qs[r * AT_STRIDE + c0 + j * 4 + 3] = __uint_as_float(f2tf(v.w * 0.125f));
        }
    }

    float m_old0 = -1e30f, m_old1 = -1e30f, l0 = 0.0f, l1 = 0.0f;
    float o[8][4];
#pragma unroll
    for (int j = 0; j < 8; j++)
#pragma unroll
        for (int r = 0; r < 4; r++) o[j][r] = 0.0f;

    for (int kv0 = 0; kv0 < T_; kv0 += 64) {
        __syncthreads();   // previous iteration's readers done (also publishes Qs)
        // stage K, V, mask
        {
            const int r  = tid >> 1;
            const int c0 = (tid & 1) * 32;
            const float* ksrc = base + E_     + (size_t)(kv0 + r) * QKV_N + c0;
            const float* vsrc = base + 2 * E_ + (size_t)(kv0 + r) * QKV_N + c0;
#pragma unroll
            for (int j = 0; j < 8; j++) {
                float4 kv = *reinterpret_cast<const float4*>(ksrc + j * 4);
                Ks[r * AT_STRIDE + c0 + j * 4 + 0] = __uint_as_float(f2tf(kv.x));
                Ks[r * AT_STRIDE + c0 + j * 4 + 1] = __uint_as_float(f2tf(kv.y));
                Ks[r * AT_STRIDE + c0 + j * 4 + 2] = __uint_as_float(f2tf(kv.z));
                Ks[r * AT_STRIDE + c0 + j * 4 + 3] = __uint_as_float(f2tf(kv.w));
                float4 vv = *reinterpret_cast<const float4*>(vsrc + j * 4);
                Vs[r * AT_STRIDE + c0 + j * 4 + 0] = __uint_as_float(f2tf(vv.x));
                Vs[r * AT_STRIDE + c0 + j * 4 + 1] = __uint_as_float(f2tf(vv.y));
                Vs[r * AT_STRIDE + c0 + j * 4 + 2] = __uint_as_float(f2tf(vv.z));
                Vs[r * AT_STRIDE + c0 + j * 4 + 3] = __uint_as_float(f2tf(vv.w));
            }
            if (tid < 64) mk[tid] = mask[b * T_ + kv0 + tid];
        }
        __syncthreads();

        // S = Q @ K^T  (64 x 64), fragments per warp: rows 16w..16w+15
        float s[8][4];
#pragma unroll
        for (int j = 0; j < 8; j++)
#pragma unroll
            for (int r = 0; r < 4; r++) s[j][r] = 0.0f;

#pragma unroll
        for (int ks = 0; ks < 8; ks++) {
            const uint32_t a0 = __float_as_uint(Qs[(16 * w + g) * AT_STRIDE + ks * 8 + t4]);
            const uint32_t a1 = __float_as_uint(Qs[(16 * w + g + 8) * AT_STRIDE + ks * 8 + t4]);
            const uint32_t a2 = __float_as_uint(Qs[(16 * w + g) * AT_STRIDE + ks * 8 + t4 + 4]);
            const uint32_t a3 = __float_as_uint(Qs[(16 * w + g + 8) * AT_STRIDE + ks * 8 + t4 + 4]);
#pragma unroll
            for (int j = 0; j < 8; j++) {
                const uint32_t b0 = __float_as_uint(Ks[(j * 8 + g) * AT_STRIDE + ks * 8 + t4]);
                const uint32_t b1 = __float_as_uint(Ks[(j * 8 + g) * AT_STRIDE + ks * 8 + t4 + 4]);
                mma_tf32(s[j], a0, a1, a2, a3, b0, b1);
            }
        }

        // mask
#pragma unroll
        for (int j = 0; j < 8; j++) {
            if (mk[j * 8 + 2 * t4] == 0)     { s[j][0] = -1e30f; s[j][2] = -1e30f; }
            if (mk[j * 8 + 2 * t4 + 1] == 0) { s[j][1] = -1e30f; s[j][3] = -1e30f; }
        }

        // online softmax (rows g and g+8 per thread; 4 lanes share a row)
        float rm0 = -1e30f, rm1 = -1e30f;
#pragma unroll
        for (int j = 0; j < 8; j++) {
            rm0 = fmaxf(rm0, fmaxf(s[j][0], s[j][1]));
            rm1 = fmaxf(rm1, fmaxf(s[j][2], s[j][3]));
        }
        rm0 = fmaxf(rm0, __shfl_xor_sync(0xffffffffu, rm0, 1));
        rm0 = fmaxf(rm0, __shfl_xor_sync(0xffffffffu, rm0, 2));
        rm1 = fmaxf(rm1, __shfl_xor_sync(0xffffffffu, rm1, 1));
        rm1 = fmaxf(rm1, __shfl_xor_sync(0xffffffffu, rm1, 2));

        const float m_new0 = fmaxf(m_old0, rm0);
        const float m_new1 = fmaxf(m_old1, rm1);
        const float alpha0 = fast_exp(m_old0 - m_new0);
        const float alpha1 = fast_exp(m_old1 - m_new1);

        float rs0 = 0.0f, rs1 = 0.0f;
#pragma unroll
        for (int j = 0; j < 8; j++) {
            s[j][0] = fast_exp(s[j][0] - m_new0); rs0 += s[j][0];
            s[j][1] = fast_exp(s[j][1] - m_new0); rs0 += s[j][1];
            s[j][2] = fast_exp(s[j][2] - m_new1); rs1 += s[j][2];
            s[j][3] = fast_exp(s[j][3] - m_new1); rs1 += s[j][3];
        }
        rs0 += __shfl_xor_sync(0xffffffffu, rs0, 1);
        rs0 += __shfl_xor_sync(0xffffffffu, rs0, 2);
        rs1 += __shfl_xor_sync(0xffffffffu, rs1, 1);
        rs1 += __shfl_xor_sync(0xffffffffu, rs1, 2);

        l0 = l0 * alpha0 + rs0;
        l1 = l1 * alpha1 + rs1;
        m_old0 = m_new0;
        m_old1 = m_new1;

#pragma unroll
        for (int j = 0; j < 8; j++) {
            o[j][0] *= alpha0; o[j][1] *= alpha0;
            o[j][2] *= alpha1; o[j][3] *= alpha1;
        }

        // P -> smem (C-fragment layout -> A-fragment layout via warp-private region)
#pragma unroll
        for (int j = 0; j < 8; j++) {
            Ps[(16 * w + g) * AT_STRIDE + j * 8 + 2 * t4]         = __uint_as_float(f2tf(s[j][0]));
            Ps[(16 * w + g) * AT_STRIDE + j * 8 + 2 * t4 + 1]     = __uint_as_float(f2tf(s[j][1]));
            Ps[(16 * w + g + 8) * AT_STRIDE + j * 8 + 2 * t4]     = __uint_as_float(f2tf(s[j][2]));
            Ps[(16 * w + g + 8) * AT_STRIDE + j * 8 + 2 * t4 + 1] = __uint_as_float(f2tf(s[j][3]));
        }
        __syncwarp();

        // O += P @ V   (A: 16 x 64 kv, B: 64 kv x 64 d)
#pragma unroll
        for (int ks = 0; ks < 8; ks++) {
            const uint32_t a0 = __float_as_uint(Ps[(16 * w + g) * AT_STRIDE + ks * 8 + t4]);
            const uint32_t a1 = __float_as_uint(Ps[(16 * w + g + 8) * AT_STRIDE + ks * 8 + t4]);
            const uint32_t a2 = __float_as_uint(Ps[(16 * w + g) * AT_STRIDE + ks * 8 + t4 + 4]);
            const uint32_t a3 = __float_as_uint(Ps[(16 * w + g + 8) * AT_STRIDE + ks * 8 + t4 + 4]);
#pragma unroll
            for (int j = 0; j < 8; j++) {
                const uint32_t b0 = __float_as_uint(Vs[(ks * 8 + t4) * AT_STRIDE + j * 8 + g]);
                const uint32_t b1 = __float_as_uint(Vs[(ks * 8 + t4 + 4) * AT_STRIDE + j * 8 + g]);
                mma_tf32(o[j], a0, a1, a2, a3, b0, b1);
            }
        }
    }

    // epilogue: O / l, store ctx[(b,t),(h,d)]  (row-major 8192 x 1024)
    const float inv0 = 1.0f / l0;
    const float inv1 = 1.0f / l1;
    float* dst = ctx + (size_t)(b * T_ + q0 + 16 * w + g) * E_ + h * D_;
#pragma unroll
    for (int j = 0; j < 8; j++) {
        dst[j * 8 + 2 * t4]                 = o[j][0] * inv0;
        dst[j * 8 + 2 * t4 + 1]             = o[j][1] * inv0;
        dst[(size_t)8 * E_ + j * 8 + 2 * t4]     = o[j][2] * inv1;
        dst[(size_t)8 * E_ + j * 8 + 2 * t4 + 1] = o[j][3] * inv1;
    }
}

// ---------------------------------------------------------------------------
// launch
// ---------------------------------------------------------------------------
extern "C" void kernel_launch(void* const* d_in, const int* in_sizes, int n_in,
                              void* d_out, int out_size) {
    (void)in_sizes; (void)n_in; (void)out_size;
    const float* x     = (const float*)d_in[0];
    const int*   mask  = (const int*)d_in[1];
    const float* W_qkv = (const float*)d_in[2];
    const float* b_qkv = (const float*)d_in[3];
    const float* W_out = (const float*)d_in[4];
    const float* b_out = (const float*)d_in[5];
    float* out = (float*)d_out;

    float *qkv_s = nullptr, *ctx_s = nullptr;
    cudaGetSymbolAddress((void**)&qkv_s, g_qkv);
    cudaGetSymbolAddress((void**)&ctx_s, g_ctx);
    cudaFuncSetAttribute(attn_kernel, cudaFuncAttributeMaxDynamicSharedMemorySize, ATTN_SMEM);

    dim3 g1(QKV_N / 128, M_ROWS / 128);
    gemm_bias_kernel<<<g1, 256>>>(x, W_qkv, b_qkv, qkv_s, M_ROWS, QKV_N, E_);

    dim3 g2(T_ / 64, H_, B_);
    attn_kernel<<<g2, 128, ATTN_SMEM>>>(qkv_s, mask, ctx_s);

    dim3 g3(E_ / 128, M_ROWS / 128);
    gemm_bias_kernel<<<g3, 256>>>(ctx_s, W_out, b_out, out, M_ROWS, E_, E_);
}

// round 3
// speedup vs baseline: 1.1573x; 1.1573x over previous
#include <cuda_runtime.h>
#include <cstdint>
#include <cstddef>

// ---------------------------------------------------------------------------
// MultiHeadAttention: x[4,2048,1024] -> out[4,2048,1024]
//   qkv = x @ W_qkv + b_qkv          (8192 x 3072, K=1024)
//   flash attention per (b,h)        (T=2048, d=64, 16 heads)
//   out = ctx @ W_out + b_out        (8192 x 1024, K=1024)
// tf32 mma.sync.m16n8k8, fp32 accumulate, cp.async double-buffered staging.
// ---------------------------------------------------------------------------

#define B_   4
#define T_   2048
#define E_   1024
#define H_   16
#define D_   64
#define M_ROWS (B_ * T_)          // 8192
#define QKV_N  (3 * E_)           // 3072

static __device__ float g_qkv[(size_t)M_ROWS * QKV_N];   // ~100.7 MB
static __device__ float g_ctx[(size_t)M_ROWS * E_];      // ~33.6 MB

// ---------------------------------------------------------------------------
// helpers
// ---------------------------------------------------------------------------
__device__ __forceinline__ uint32_t f2tf(float f) {
    uint32_t u;
    asm("cvt.rna.tf32.f32 %0, %1;" : "=r"(u) : "f"(f));
    return u;
}

__device__ __forceinline__ void mma_tf32(float c[4],
                                         uint32_t a0, uint32_t a1, uint32_t a2, uint32_t a3,
                                         uint32_t b0, uint32_t b1) {
    asm volatile(
        "mma.sync.aligned.m16n8k8.row.col.f32.tf32.tf32.f32 "
        "{%0,%1,%2,%3}, {%4,%5,%6,%7}, {%8,%9}, {%0,%1,%2,%3};"
        : "+f"(c[0]), "+f"(c[1]), "+f"(c[2]), "+f"(c[3])
        : "r"(a0), "r"(a1), "r"(a2), "r"(a3), "r"(b0), "r"(b1));
}

__device__ __forceinline__ void cp16(void* smem_dst, const void* gsrc) {
    uint32_t s = (uint32_t)__cvta_generic_to_shared(smem_dst);
    asm volatile("cp.async.cg.shared.global [%0], [%1], 16;" :: "r"(s), "l"(gsrc));
}
__device__ __forceinline__ void cp_commit() { asm volatile("cp.async.commit_group;"); }
__device__ __forceinline__ void cp_wait_all() { asm volatile("cp.async.wait_group 0;"); }

// FMA-only exp (avoids MUFU bottleneck: 268M exps in softmax).
__device__ __forceinline__ float fast_exp(float x) {
    x = fmaxf(x, -87.0f);
    const float L2E = 1.4426950408889634f;
    float z  = fmaf(x, L2E, 12582912.0f);
    int   ni = __float_as_int(z) - 0x4B400000;
    float n  = z - 12582912.0f;
    float f  = fmaf(x, L2E, -n);
    float p  = fmaf(f, 0.0013333558f, 0.0096181291f);
    p = fmaf(f, p, 0.0555041087f);
    p = fmaf(f, p, 0.2402265070f);
    p = fmaf(f, p, 0.6931471806f);
    p = fmaf(f, p, 1.0f);
    return p * __int_as_float((ni + 127) << 23);
}

// ---------------------------------------------------------------------------
// GEMM: C[M,N] = A[M,K] @ W[K,N] + bias[N]  (128x128x32 tiles, 8 warps)
// cp.async double-buffered; raw fp32 staged; cvt.rna at fragment load.
// Pitches: GA=36 (36%32=4 -> bank 4g+t4, conflict-free), GB=136 (8t4+g, cf).
// ---------------------------------------------------------------------------
#define GA_P 36
#define GB_P 136
#define GEMM_SMEM ((2 * 128 * GA_P + 2 * 32 * GB_P) * 4)

__global__ __launch_bounds__(256)
void gemm_bias_kernel(const float* __restrict__ A, const float* __restrict__ W,
                      const float* __restrict__ bias, float* __restrict__ C,
                      int M, int N, int K) {
    extern __shared__ float sm[];
    float* As = sm;                      // [2][128*GA_P]
    float* Bs = sm + 2 * 128 * GA_P;     // [2][32*GB_P]

    const int tid   = threadIdx.x;
    const int lane  = tid & 31;
    const int w     = tid >> 5;
    const int g     = lane >> 2;
    const int t4    = lane & 3;
    const int warpM = w >> 2;
    const int warpN = w & 3;
    const int bm    = blockIdx.y * 128;
    const int bn    = blockIdx.x * 128;

    const int am  = tid >> 3;        // 0..31
    const int ak  = (tid & 7) * 4;   // 0..28
    const int bn4 = (tid & 31) * 4;  // col
    const int bk  = tid >> 5;        // 0..7

    float c[4][4][4];
#pragma unroll
    for (int mt = 0; mt < 4; mt++)
#pragma unroll
        for (int nt = 0; nt < 4; nt++)
#pragma unroll
            for (int r = 0; r < 4; r++) c[mt][nt][r] = 0.0f;

    const int NIT = K / 32;

    // prologue: stage 0
    {
#pragma unroll
        for (int p = 0; p < 4; p++) {
            const int m = am + p * 32;
            cp16(&As[m * GA_P + ak], &A[(size_t)(bm + m) * K + ak]);
        }
#pragma unroll
        for (int p = 0; p < 4; p++) {
            const int kk = bk + p * 8;
            cp16(&Bs[kk * GB_P + bn4], &W[(size_t)kk * N + bn + bn4]);
        }
        cp_commit();
    }

    for (int it = 0; it < NIT; it++) {
        const int buf = it & 1;
        cp_wait_all();
        __syncthreads();

        if (it + 1 < NIT) {
            const int nb = (it + 1) & 1;
            const int k0 = (it + 1) * 32;
            float* Ad = As + nb * 128 * GA_P;
            float* Bd = Bs + nb * 32 * GB_P;
#pragma unroll
            for (int p = 0; p < 4; p++) {
                const int m = am + p * 32;
                cp16(&Ad[m * GA_P + ak], &A[(size_t)(bm + m) * K + k0 + ak]);
            }
#pragma unroll
            for (int p = 0; p < 4; p++) {
                const int kk = bk + p * 8;
                cp16(&Bd[kk * GB_P + bn4], &W[(size_t)(k0 + kk) * N + bn + bn4]);
            }
            cp_commit();
        }

        const float* Ab = As + buf * 128 * GA_P;
        const float* Bb = Bs + buf * 32 * GB_P;

#pragma unroll
        for (int ks = 0; ks < 4; ks++) {
            uint32_t a[4][4];
#pragma unroll
            for (int mt = 0; mt < 4; mt++) {
                const int r = warpM * 64 + mt * 16 + g;
                a[mt][0] = f2tf(Ab[r * GA_P + ks * 8 + t4]);
                a[mt][1] = f2tf(Ab[(r + 8) * GA_P + ks * 8 + t4]);
                a[mt][2] = f2tf(Ab[r * GA_P + ks * 8 + t4 + 4]);
                a[mt][3] = f2tf(Ab[(r + 8) * GA_P + ks * 8 + t4 + 4]);
            }
            uint32_t bf[4][2];
#pragma unroll
            for (int nt = 0; nt < 4; nt++) {
                const int cn = warpN * 32 + nt * 8 + g;
                bf[nt][0] = f2tf(Bb[(ks * 8 + t4) * GB_P + cn]);
                bf[nt][1] = f2tf(Bb[(ks * 8 + t4 + 4) * GB_P + cn]);
            }
#pragma unroll
            for (int mt = 0; mt < 4; mt++)
#pragma unroll
                for (int nt = 0; nt < 4; nt++)
                    mma_tf32(c[mt][nt], a[mt][0], a[mt][1], a[mt][2], a[mt][3],
                             bf[nt][0], bf[nt][1]);
        }
        // no trailing barrier: next iteration's wait+sync covers the WAR hazard
    }

    // epilogue
#pragma unroll
    for (int mt = 0; mt < 4; mt++) {
        const int r0 = bm + warpM * 64 + mt * 16 + g;
#pragma unroll
        for (int nt = 0; nt < 4; nt++) {
            const int cn = bn + warpN * 32 + nt * 8 + 2 * t4;
            const float bv0 = bias[cn], bv1 = bias[cn + 1];
            C[(size_t)r0 * N + cn]           = c[mt][nt][0] + bv0;
            C[(size_t)r0 * N + cn + 1]       = c[mt][nt][1] + bv1;
            C[(size_t)(r0 + 8) * N + cn]     = c[mt][nt][2] + bv0;
            C[(size_t)(r0 + 8) * N + cn + 1] = c[mt][nt][3] + bv1;
        }
    }
}

// ---------------------------------------------------------------------------
// Flash attention. Block = (b, h, 64 q-rows), 128 threads (4 warps x 16 q).
// Q fragments register-resident for whole kv loop. K/V staged raw fp32 via
// cp.async (double-buffered), cvt.rna at fragment load. Pitch 68 -> bank
// 4g+t4: conflict-free fragment loads. ~85.5 KB smem -> 2 CTAs/SM.
// ---------------------------------------------------------------------------
#define AT_P 68
#define TILE_F (64 * AT_P)
#define ATTN_SMEM (5 * TILE_F * 4 + 2 * 64 * 4)

__global__ __launch_bounds__(128)
void attn_kernel(const float* __restrict__ qkv, const int* __restrict__ mask,
                 float* __restrict__ ctx) {
    extern __shared__ float sm[];
    float* Ks0 = sm;                    // [2][TILE_F]
    float* Vs0 = sm + 2 * TILE_F;       // [2][TILE_F]
    float* Ps  = sm + 4 * TILE_F;       // [TILE_F] (Q staging, then P)
    int*   mk  = (int*)(sm + 5 * TILE_F); // [2][64]

    const int b  = blockIdx.z;
    const int h  = blockIdx.y;
    const int q0 = blockIdx.x * 64;
    const int tid = threadIdx.x, lane = tid & 31, w = tid >> 5;
    const int g = lane >> 2, t4 = lane & 3;

    const float* base  = qkv + (size_t)b * T_ * QKV_N + h * D_;
    const float* kbase = base + E_;
    const float* vbase = base + 2 * E_;

    const int sr  = tid >> 1;          // staging row 0..63
    const int sc0 = (tid & 1) * 32;    // staging col base

    // prologue: stage kv-tile 0 (K, V, mask) via cp.async
    {
        const float* ks = kbase + (size_t)sr * QKV_N + sc0;
        const float* vs = vbase + (size_t)sr * QKV_N + sc0;
#pragma unroll
        for (int j = 0; j < 8; j++) {
            cp16(&Ks0[sr * AT_P + sc0 + j * 4], ks + j * 4);
            cp16(&Vs0[sr * AT_P + sc0 + j * 4], vs + j * 4);
        }
        if (tid < 16) cp16(&mk[tid * 4], mask + b * T_ + tid * 4);
        cp_commit();
    }

    // stage Q (scaled, tf32) into Ps
    {
        const float* src = base + (size_t)(q0 + sr) * QKV_N + sc0;
#pragma unroll
        for (int j = 0; j < 8; j++) {
            float4 v = *reinterpret_cast<const float4*>(src + j * 4);
            Ps[sr * AT_P + sc0 + j * 4 + 0] = __uint_as_float(f2tf(v.x * 0.125f));
            Ps[sr * AT_P + sc0 + j * 4 + 1] = __uint_as_float(f2tf(v.y * 0.125f));
            Ps[sr * AT_P + sc0 + j * 4 + 2] = __uint_as_float(f2tf(v.z * 0.125f));
            Ps[sr * AT_P + sc0 + j * 4 + 3] = __uint_as_float(f2tf(v.w * 0.125f));
        }
    }
    __syncthreads();

    // hoist Q fragments into registers for the entire kv loop
    uint32_t q[8][4];
#pragma unroll
    for (int ks = 0; ks < 8; ks++) {
        q[ks][0] = __float_as_uint(Ps[(16 * w + g) * AT_P + ks * 8 + t4]);
        q[ks][1] = __float_as_uint(Ps[(16 * w + g + 8) * AT_P + ks * 8 + t4]);
        q[ks][2] = __float_as_uint(Ps[(16 * w + g) * AT_P + ks * 8 + t4 + 4]);
        q[ks][3] = __float_as_uint(Ps[(16 * w + g + 8) * AT_P + ks * 8 + t4 + 4]);
    }

    float m_old0 = -1e30f, m_old1 = -1e30f, l0 = 0.0f, l1 = 0.0f;
    float o[8][4];
#pragma unroll
    for (int j = 0; j < 8; j++)
#pragma unroll
        for (int r = 0; r < 4; r++) o[j][r] = 0.0f;

    for (int it = 0; it < T_ / 64; it++) {
        const int buf = it & 1;
        cp_wait_all();
        __syncthreads();   // staged data visible; prev compute done -> other buf free

        if (it + 1 < T_ / 64) {
            const int nb = (it + 1) & 1;
            const int kv = (it + 1) * 64;
            const float* ks = kbase + (size_t)(kv + sr) * QKV_N + sc0;
            const float* vs = vbase + (size_t)(kv + sr) * QKV_N + sc0;
            float* Kd = Ks0 + nb * TILE_F;
            float* Vd = Vs0 + nb * TILE_F;
#pragma unroll
            for (int j = 0; j < 8; j++) {
                cp16(&Kd[sr * AT_P + sc0 + j * 4], ks + j * 4);
                cp16(&Vd[sr * AT_P + sc0 + j * 4], vs + j * 4);
            }
            if (tid < 16) cp16(&mk[nb * 64 + tid * 4], mask + b * T_ + kv + tid * 4);
            cp_commit();
        }

        const float* Ksb = Ks0 + buf * TILE_F;
        const float* Vsb = Vs0 + buf * TILE_F;
        const int*   mkb = mk + buf * 64;

        // S = Q @ K^T (64x64)
        float s[8][4];
#pragma unroll
        for (int j = 0; j < 8; j++)
#pragma unroll
            for (int r = 0; r < 4; r++) s[j][r] = 0.0f;

#pragma unroll
        for (int ks = 0; ks < 8; ks++) {
#pragma unroll
            for (int j = 0; j < 8; j++) {
                const uint32_t b0 = f2tf(Ksb[(j * 8 + g) * AT_P + ks * 8 + t4]);
                const uint32_t b1 = f2tf(Ksb[(j * 8 + g) * AT_P + ks * 8 + t4 + 4]);
                mma_tf32(s[j], q[ks][0], q[ks][1], q[ks][2], q[ks][3], b0, b1);
            }
        }

        // mask
#pragma unroll
        for (int j = 0; j < 8; j++) {
            if (mkb[j * 8 + 2 * t4] == 0)     { s[j][0] = -1e30f; s[j][2] = -1e30f; }
            if (mkb[j * 8 + 2 * t4 + 1] == 0) { s[j][1] = -1e30f; s[j][3] = -1e30f; }
        }

        // online softmax
        float rm0 = -1e30f, rm1 = -1e30f;
#pragma unroll
        for (int j = 0; j < 8; j++) {
            rm0 = fmaxf(rm0, fmaxf(s[j][0], s[j][1]));
            rm1 = fmaxf(rm1, fmaxf(s[j][2], s[j][3]));
        }
        rm0 = fmaxf(rm0, __shfl_xor_sync(0xffffffffu, rm0, 1));
        rm0 = fmaxf(rm0, __shfl_xor_sync(0xffffffffu, rm0, 2));
        rm1 = fmaxf(rm1, __shfl_xor_sync(0xffffffffu, rm1, 1));
        rm1 = fmaxf(rm1, __shfl_xor_sync(0xffffffffu, rm1, 2));

        const float m_new0 = fmaxf(m_old0, rm0);
        const float m_new1 = fmaxf(m_old1, rm1);
        const float alpha0 = fast_exp(m_old0 - m_new0);
        const float alpha1 = fast_exp(m_old1 - m_new1);

        float rs0 = 0.0f, rs1 = 0.0f;
#pragma unroll
        for (int j = 0; j < 8; j++) {
            s[j][0] = fast_exp(s[j][0] - m_new0); rs0 += s[j][0];
            s[j][1] = fast_exp(s[j][1] - m_new0); rs0 += s[j][1];
            s[j][2] = fast_exp(s[j][2] - m_new1); rs1 += s[j][2];
            s[j][3] = fast_exp(s[j][3] - m_new1); rs1 += s[j][3];
        }
        rs0 += __shfl_xor_sync(0xffffffffu, rs0, 1);
        rs0 += __shfl_xor_sync(0xffffffffu, rs0, 2);
        rs1 += __shfl_xor_sync(0xffffffffu, rs1, 1);
        rs1 += __shfl_xor_sync(0xffffffffu, rs1, 2);

        l0 = l0 * alpha0 + rs0;
        l1 = l1 * alpha1 + rs1;
        m_old0 = m_new0;
        m_old1 = m_new1;

#pragma unroll
        for (int j = 0; j < 8; j++) {
            o[j][0] *= alpha0; o[j][1] *= alpha0;
            o[j][2] *= alpha1; o[j][3] *= alpha1;
        }

        // P -> smem (warp-private rows), reload as A-fragments
#pragma unroll
        for (int j = 0; j < 8; j++) {
            Ps[(16 * w + g) * AT_P + j * 8 + 2 * t4]         = __uint_as_float(f2tf(s[j][0]));
            Ps[(16 * w + g) * AT_P + j * 8 + 2 * t4 + 1]     = __uint_as_float(f2tf(s[j][1]));
            Ps[(16 * w + g + 8) * AT_P + j * 8 + 2 * t4]     = __uint_as_float(f2tf(s[j][2]));
            Ps[(16 * w + g + 8) * AT_P + j * 8 + 2 * t4 + 1] = __uint_as_float(f2tf(s[j][3]));
        }
        __syncwarp();

        // O += P @ V
#pragma unroll
        for (int ks = 0; ks < 8; ks++) {
            const uint32_t a0 = __float_as_uint(Ps[(16 * w + g) * AT_P + ks * 8 + t4]);
            const uint32_t a1 = __float_as_uint(Ps[(16 * w + g + 8) * AT_P + ks * 8 + t4]);
            const uint32_t a2 = __float_as_uint(Ps[(16 * w + g) * AT_P + ks * 8 + t4 + 4]);
            const uint32_t a3 = __float_as_uint(Ps[(16 * w + g + 8) * AT_P + ks * 8 + t4 + 4]);
#pragma unroll
            for (int j = 0; j < 8; j++) {
                const uint32_t b0 = f2tf(Vsb[(ks * 8 + t4) * AT_P + j * 8 + g]);
                const uint32_t b1 = f2tf(Vsb[(ks * 8 + t4 + 4) * AT_P + j * 8 + g]);
                mma_tf32(o[j], a0, a1, a2, a3, b0, b1);
            }
        }
        __syncthreads();  // all warps done reading buf before it is re-staged
    }

    // epilogue
    const float inv0 = 1.0f / l0;
    const float inv1 = 1.0f / l1;
    float* dst = ctx + (size_t)(b * T_ + q0 + 16 * w + g) * E_ + h * D_;
#pragma unroll
    for (int j = 0; j < 8; j++) {
        dst[j * 8 + 2 * t4]                      = o[j][0] * inv0;
        dst[j * 8 + 2 * t4 + 1]                  = o[j][1] * inv0;
        dst[(size_t)8 * E_ + j * 8 + 2 * t4]     = o[j][2] * inv1;
        dst[(size_t)8 * E_ + j * 8 + 2 * t4 + 1] = o[j][3] * inv1;
    }
}

// ---------------------------------------------------------------------------
// launch (no static guards: every call is identical per harness contract)
// ---------------------------------------------------------------------------
extern "C" void kernel_launch(void* const* d_in, const int* in_sizes, int n_in,
                              void* d_out, int out_size) {
    (void)in_sizes; (void)n_in; (void)out_size;
    const float* x     = (const float*)d_in[0];
    const int*   mask  = (const int*)d_in[1];
    const float* W_qkv = (const float*)d_in[2];
    const float* b_qkv = (const float*)d_in[3];
    const float* W_out = (const float*)d_in[4];
    const float* b_out = (const float*)d_in[5];
    float* out = (float*)d_out;

    float *qkv_s = nullptr, *ctx_s = nullptr;
    cudaGetSymbolAddress((void**)&qkv_s, g_qkv);
    cudaGetSymbolAddress((void**)&ctx_s, g_ctx);

    cudaFuncSetAttribute(gemm_bias_kernel, cudaFuncAttributeMaxDynamicSharedMemorySize, GEMM_SMEM);
    cudaFuncSetAttribute(attn_kernel, cudaFuncAttributeMaxDynamicSharedMemorySize, ATTN_SMEM);

    dim3 g1(QKV_N / 128, M_ROWS / 128);
    gemm_bias_kernel<<<g1, 256, GEMM_SMEM>>>(x, W_qkv, b_qkv, qkv_s, M_ROWS, QKV_N, E_);

    dim3 g2(T_ / 64, H_, B_);
    attn_kernel<<<g2, 128, ATTN_SMEM>>>(qkv_s, mask, ctx_s);

    dim3 g3(E_ / 128, M_ROWS / 128);
    gemm_bias_kernel<<<g3, 256, GEMM_SMEM>>>(ctx_s, W_out, b_out, out, M_ROWS, E_, E_);
}